// round 5
// baseline (speedup 1.0000x reference)
#include <cuda_runtime.h>
#include <cstdint>

#define CC_ 32
#define HH 128
#define WW 128
#define FF 64
#define ORR 64
#define OCC 64

#define PX 16                         // 2 rows x 8 input cols per tile
#define XS_STRIDE 36
#define WS_STRIDE 68
#define XS_BUF (4*PX*XS_STRIDE)       // floats per buffer (4 channels/stage)
#define WS_BUF (4*PX*WS_STRIDE)
#define SMEM_BYTES ((2*XS_BUF + 2*WS_BUF) * 4)   // 53248 B

__device__ __forceinline__ void fma2(unsigned long long& d,
                                     unsigned long long a,
                                     unsigned long long b) {
    asm("fma.rn.f32x2 %0, %1, %2, %3;" : "=l"(d) : "l"(a), "l"(b), "l"(d));
}
__device__ __forceinline__ unsigned long long bcast2(float v) {
    unsigned long long r;
    unsigned int u = __float_as_uint(v);
    asm("mov.b64 %0, {%1, %1};" : "=l"(r) : "r"(u));
    return r;
}
__device__ __forceinline__ void cp4(uint32_t dst, const float* src) {
    asm volatile("cp.async.ca.shared.global [%0], [%1], 4;"
                 :: "r"(dst), "l"(src));
}

__global__ __launch_bounds__(256, 3)
void lc2d_kernel(const float* __restrict__ x,
                 const float* __restrict__ w,
                 const float* __restrict__ bias,
                 float* __restrict__ out) {
    extern __shared__ float smem[];
    float* xs = smem;                // [buf][cc4][px16][36]
    float* ws = smem + 2 * XS_BUF;   // [buf][cc4][px16][68]

    const int tid  = threadIdx.x;
    const int or_  = blockIdx.y;
    const int oct0 = blockIdx.x * 4;
    const int h0   = or_ * 2;
    const int w0   = oct0 * 2;

    // compute-side mapping
    const int g    = tid >> 6;
    const int r    = tid & 63;
    const int bsub = r & 7;
    const int fsub = r >> 3;

    // loader-side mapping
    const int xcol = tid & 7;
    const int xb   = tid >> 3;
    const int wsv  = tid & 3;
    const int wf   = tid >> 2;

    const float* xg = x + (xb * CC_ * HH + h0) * WW + w0 + xcol;
    const float* wg = w + (wf * CC_ * HH + h0) * WW + w0 + 2 * wsv;

    // per-thread cp.async destination bases (byte addresses in shared space)
    const uint32_t xs_u = (uint32_t)__cvta_generic_to_shared(xs);
    const uint32_t ws_u = (uint32_t)__cvta_generic_to_shared(ws);
    // x dst (per rr): row = cc*PX + rr*8 + xcol, col = xb
    const uint32_t xd0 = xs_u + (uint32_t)(((0 * 8 + xcol) * XS_STRIDE + xb) * 4);
    const uint32_t xd1 = xs_u + (uint32_t)(((1 * 8 + xcol) * XS_STRIDE + xb) * 4);
    // w dst (per rr, per col k): row = cc*PX + rr*8 + 2wsv + k, col = wf
    const uint32_t wd00 = ws_u + (uint32_t)(((0 * 8 + 2 * wsv)     * WS_STRIDE + wf) * 4);
    const uint32_t wd01 = ws_u + (uint32_t)(((0 * 8 + 2 * wsv + 1) * WS_STRIDE + wf) * 4);
    const uint32_t wd10 = ws_u + (uint32_t)(((1 * 8 + 2 * wsv)     * WS_STRIDE + wf) * 4);
    const uint32_t wd11 = ws_u + (uint32_t)(((1 * 8 + 2 * wsv + 1) * WS_STRIDE + wf) * 4);

    unsigned long long acc[4][4];
#pragma unroll
    for (int i = 0; i < 4; ++i)
#pragma unroll
        for (int j = 0; j < 4; ++j) acc[i][j] = 0ull;

    // ---- issue helper: stage of 4 channels [cn, cn+4) into buffer `buf` ----
    auto issue_stage = [&](int cn, int buf) {
        const uint32_t xo = (uint32_t)(buf * XS_BUF * 4);
        const uint32_t wo = (uint32_t)(buf * WS_BUF * 4);
#pragma unroll
        for (int cc = 0; cc < 4; ++cc) {
            const uint32_t crow = (uint32_t)(cc * PX * 4);  // row block offset in floats*4
            const float* xrow0 = xg + ((cn + cc) * HH + 0) * WW;
            const float* xrow1 = xg + ((cn + cc) * HH + 1) * WW;
            const float* wrow0 = wg + ((cn + cc) * HH + 0) * WW;
            const float* wrow1 = wg + ((cn + cc) * HH + 1) * WW;
            cp4(xo + xd0 + crow * XS_STRIDE, xrow0);
            cp4(xo + xd1 + crow * XS_STRIDE, xrow1);
            cp4(wo + wd00 + crow * WS_STRIDE, wrow0);
            cp4(wo + wd01 + crow * WS_STRIDE, wrow0 + 1);
            cp4(wo + wd10 + crow * WS_STRIDE, wrow1);
            cp4(wo + wd11 + crow * WS_STRIDE, wrow1 + 1);
        }
        asm volatile("cp.async.commit_group;");
    };

    // ---- prologue: issue stage 0 ----
    issue_stage(0, 0);

    // pixel row offsets for this thread's pooled group (compile-time folded)
    for (int s = 0; s < 8; ++s) {
        const int cur = s & 1;

        // wait for buffer `cur` (the only outstanding group), make visible
        asm volatile("cp.async.wait_group 0;");
        __syncthreads();

        // issue next stage into the other buffer (safe: everyone passed the
        // barrier, so all reads of that buffer from stage s-1 are complete)
        if (s + 1 < 8) issue_stage((s + 1) * 4, cur ^ 1);

        // ---- compute on buffer cur: 16 iterations, software-pipelined ----
        const float* xsb = xs + cur * XS_BUF;
        const float* wsb = ws + cur * WS_BUF;

        float4 xa;
        ulonglong2 wq0, wq1;
        {
            const int row0 = 0 * PX + 2 * g;   // t=0: cc=0, pp=0
            xa  = *(const float4*)&xsb[row0 * XS_STRIDE + bsub * 4];
            wq0 = *(const ulonglong2*)&wsb[row0 * WS_STRIDE + fsub * 8];
            wq1 = *(const ulonglong2*)&wsb[row0 * WS_STRIDE + fsub * 8 + 4];
        }
#pragma unroll
        for (int t = 0; t < 16; ++t) {
            float4 xn;
            ulonglong2 wn0, wn1;
            if (t + 1 < 16) {
                const int tn = t + 1;
                const int cc = tn >> 2, pp = tn & 3;
                const int row = cc * PX + (pp >> 1) * 8 + 2 * g + (pp & 1);
                xn  = *(const float4*)&xsb[row * XS_STRIDE + bsub * 4];
                wn0 = *(const ulonglong2*)&wsb[row * WS_STRIDE + fsub * 8];
                wn1 = *(const ulonglong2*)&wsb[row * WS_STRIDE + fsub * 8 + 4];
            }
            const float xv[4] = {xa.x, xa.y, xa.z, xa.w};
#pragma unroll
            for (int bi = 0; bi < 4; ++bi) {
                const unsigned long long xb2 = bcast2(xv[bi]);
                fma2(acc[bi][0], xb2, wq0.x);
                fma2(acc[bi][1], xb2, wq0.y);
                fma2(acc[bi][2], xb2, wq1.x);
                fma2(acc[bi][3], xb2, wq1.y);
            }
            xa = xn; wq0 = wn0; wq1 = wn1;
        }
    }

    // ---- epilogue: bias (raw keras reshape) + relu + store ----
    const int oc = oct0 + g;
    const float* bp = bias + or_ * OCC + oc;
    float bvv[8];
#pragma unroll
    for (int j = 0; j < 4; ++j) {
        const int f0 = fsub * 8 + 2 * j;
        bvv[2 * j]     = bp[f0 * (ORR * OCC)];
        bvv[2 * j + 1] = bp[(f0 + 1) * (ORR * OCC)];
    }
#pragma unroll
    for (int bi = 0; bi < 4; ++bi) {
        const int b_ = bsub * 4 + bi;
        float* op = out + ((b_ * FF) * ORR + or_) * OCC + oc;
#pragma unroll
        for (int j = 0; j < 4; ++j) {
            const int f0 = fsub * 8 + 2 * j;
            unsigned int lo, hi;
            asm("mov.b64 {%0, %1}, %2;" : "=r"(lo), "=r"(hi) : "l"(acc[bi][j]));
            const float v0 = __uint_as_float(lo) + bvv[2 * j];
            const float v1 = __uint_as_float(hi) + bvv[2 * j + 1];
            op[f0 * (ORR * OCC)]       = fmaxf(v0, 0.f);
            op[(f0 + 1) * (ORR * OCC)] = fmaxf(v1, 0.f);
        }
    }
}

extern "C" void kernel_launch(void* const* d_in, const int* in_sizes, int n_in,
                              void* d_out, int out_size) {
    const float* x    = (const float*)d_in[0];
    const float* w    = (const float*)d_in[1];
    const float* bias = (const float*)d_in[2];
    float* out        = (float*)d_out;

    cudaFuncSetAttribute(lc2d_kernel,
                         cudaFuncAttributeMaxDynamicSharedMemorySize, SMEM_BYTES);

    dim3 grid(OCC / 4, ORR, 1);
    lc2d_kernel<<<grid, 256, SMEM_BYTES>>>(x, w, bias, out);
}

// round 6
// speedup vs baseline: 1.8650x; 1.8650x over previous
#include <cuda_runtime.h>
#include <cstdint>

#define KA 12                 // k-stride (8 + 4 pad) -> conflict-free fragment LDS
#define AWS 388               // 32*KA + 4  (warp panel stride, A)
#define BWS 772               // 64*KA + 4  (warp panel stride, B)
#define ABUF (8*AWS)          // 3104 floats per A buffer
#define BBUF (8*BWS)          // 6176 floats per B buffer
#define OSM_ROW 581           // 64*9 + 5 (epilogue transpose row stride)
#define SMEM_FLOATS 18592
#define SMEM_BYTES (SMEM_FLOATS*4)

#define PSTEP (16*32*16384)   // +16 in b/f dimension (floats)
#define CSTEP (2*16384)       // +1 stage = +2 channels (floats)

__device__ __forceinline__ uint32_t f2tf32(float f) {
    uint32_t u; asm("cvt.rna.tf32.f32 %0, %1;" : "=r"(u) : "f"(f)); return u;
}
__device__ __forceinline__ void mma_tf32(float& d0, float& d1, float& d2, float& d3,
                                         uint32_t a0, uint32_t a1, uint32_t a2, uint32_t a3,
                                         uint32_t b0, uint32_t b1) {
    asm("mma.sync.aligned.m16n8k8.row.col.f32.tf32.tf32.f32 "
        "{%0,%1,%2,%3},{%4,%5,%6,%7},{%8,%9},{%0,%1,%2,%3};"
        : "+f"(d0), "+f"(d1), "+f"(d2), "+f"(d3)
        : "r"(a0), "r"(a1), "r"(a2), "r"(a3), "r"(b0), "r"(b1));
}

__global__ __launch_bounds__(256, 2)
void lc2d_kernel(const float* __restrict__ x,
                 const float* __restrict__ w,
                 const float* __restrict__ bias,
                 float* __restrict__ out) {
    extern __shared__ float sm[];
    float* AS = sm;                 // [2][warp8][b32][KA]
    float* BS = sm + 2 * ABUF;      // [2][warp8][f64][KA]

    const int tid  = threadIdx.x;
    const int or_  = blockIdx.y;
    const int oct0 = blockIdx.x * 8;
    const int h0   = or_ * 2;
    const int w0   = oct0 * 2;

    // ---- loader mapping: tid -> (colq, row, c_local, b-or-f) ----
    const int colq = tid & 3;            // float4 index along 16 input cols
    const int lrow = (tid >> 2) & 1;     // input row within pooled row
    const int lcl  = (tid >> 3) & 1;     // channel within stage
    const int lb   = tid >> 4;           // 0..15 : b (for x) / f (for W)

    const float* xp = x + ((lb * 32 + lcl) * 128 + h0 + lrow) * 128 + w0 + 4 * colq;
    const float* wp = w + ((lb * 32 + lcl) * 128 + h0 + lrow) * 128 + w0 + 4 * colq;

    // STS offsets: col = 4*colq + e ; wp_e = col>>1 ; cp = col&1 ; k = lcl*4+lrow*2+cp
    int a_off[2][4], b_off[4][4];
#pragma unroll
    for (int e = 0; e < 4; ++e) {
        const int wpe = 2 * colq + (e >> 1);
        const int k   = lcl * 4 + lrow * 2 + (e & 1);
#pragma unroll
        for (int i = 0; i < 2; ++i)
            a_off[i][e] = wpe * AWS + (lb + 16 * i) * KA + k;
#pragma unroll
        for (int i = 0; i < 4; ++i)
            b_off[i][e] = wpe * BWS + (lb + 16 * i) * KA + k;
    }

    // ---- mma mapping ----
    const int lane = tid & 31, wid = tid >> 5;
    const int g = lane >> 2, t = lane & 3;

    int a_ld[2][4];
#pragma unroll
    for (int mt = 0; mt < 2; ++mt) {
        a_ld[mt][0] = wid * AWS + (mt * 16 + g)     * KA + t;
        a_ld[mt][1] = wid * AWS + (mt * 16 + g + 8) * KA + t;
        a_ld[mt][2] = a_ld[mt][0] + 4;
        a_ld[mt][3] = a_ld[mt][1] + 4;
    }

    float acc[2][8][4];
#pragma unroll
    for (int mt = 0; mt < 2; ++mt)
#pragma unroll
        for (int nt = 0; nt < 8; ++nt)
#pragma unroll
            for (int r = 0; r < 4; ++r) acc[mt][nt][r] = 0.f;

    float4 xr[2], wr[4];

    // ---- prologue: load + stage 0 ----
#pragma unroll
    for (int i = 0; i < 2; ++i) xr[i] = *(const float4*)(xp + i * PSTEP);
#pragma unroll
    for (int i = 0; i < 4; ++i) wr[i] = *(const float4*)(wp + i * PSTEP);
#pragma unroll
    for (int i = 0; i < 2; ++i) {
        const float v[4] = {xr[i].x, xr[i].y, xr[i].z, xr[i].w};
#pragma unroll
        for (int e = 0; e < 4; ++e)
            AS[a_off[i][e]] = __uint_as_float(f2tf32(v[e]));
    }
#pragma unroll
    for (int i = 0; i < 4; ++i) {
        const float v[4] = {wr[i].x, wr[i].y, wr[i].z, wr[i].w};
#pragma unroll
        for (int e = 0; e < 4; ++e)
            BS[b_off[i][e]] = __uint_as_float(f2tf32(v[e]));
    }
    __syncthreads();

    // ---- main loop: 16 stages of 2 channels ----
    for (int s = 0; s < 16; ++s) {
        const int buf = s & 1;

        if (s < 15) {
            const int off = (s + 1) * CSTEP;
#pragma unroll
            for (int i = 0; i < 2; ++i) xr[i] = *(const float4*)(xp + off + i * PSTEP);
#pragma unroll
            for (int i = 0; i < 4; ++i) wr[i] = *(const float4*)(wp + off + i * PSTEP);
        }

        const float* Ap = AS + buf * ABUF;
        const float* Bp = BS + buf * BBUF + wid * BWS;

        uint32_t a[2][4];
#pragma unroll
        for (int mt = 0; mt < 2; ++mt)
#pragma unroll
            for (int r = 0; r < 4; ++r)
                a[mt][r] = __float_as_uint(Ap[a_ld[mt][r]]);

#pragma unroll
        for (int nt = 0; nt < 8; ++nt) {
            const uint32_t b0 = __float_as_uint(Bp[(nt * 8 + g) * KA + t]);
            const uint32_t b1 = __float_as_uint(Bp[(nt * 8 + g) * KA + t + 4]);
            mma_tf32(acc[0][nt][0], acc[0][nt][1], acc[0][nt][2], acc[0][nt][3],
                     a[0][0], a[0][1], a[0][2], a[0][3], b0, b1);
            mma_tf32(acc[1][nt][0], acc[1][nt][1], acc[1][nt][2], acc[1][nt][3],
                     a[1][0], a[1][1], a[1][2], a[1][3], b0, b1);
        }

        if (s < 15) {
            float* An = AS + (buf ^ 1) * ABUF;
            float* Bn = BS + (buf ^ 1) * BBUF;
#pragma unroll
            for (int i = 0; i < 2; ++i) {
                const float v[4] = {xr[i].x, xr[i].y, xr[i].z, xr[i].w};
#pragma unroll
                for (int e = 0; e < 4; ++e)
                    An[a_off[i][e]] = __uint_as_float(f2tf32(v[e]));
            }
#pragma unroll
            for (int i = 0; i < 4; ++i) {
                const float v[4] = {wr[i].x, wr[i].y, wr[i].z, wr[i].w};
#pragma unroll
                for (int e = 0; e < 4; ++e)
                    Bn[b_off[i][e]] = __uint_as_float(f2tf32(v[e]));
            }
        }
        __syncthreads();
    }

    // ---- epilogue: transpose through smem, bias + relu, coalesced STG ----
    float* OS = sm;   // safe: last stage ended with __syncthreads()
#pragma unroll
    for (int mt = 0; mt < 2; ++mt)
#pragma unroll
        for (int nt = 0; nt < 8; ++nt) {
            const int r0 = mt * 16 + g;
            const int c0 = nt * 8 + 2 * t;
            OS[r0 * OSM_ROW + c0 * 9 + wid]           = acc[mt][nt][0];
            OS[r0 * OSM_ROW + (c0 + 1) * 9 + wid]     = acc[mt][nt][1];
            OS[(r0 + 8) * OSM_ROW + c0 * 9 + wid]     = acc[mt][nt][2];
            OS[(r0 + 8) * OSM_ROW + (c0 + 1) * 9 + wid] = acc[mt][nt][3];
        }
    __syncthreads();

    const float* bb = bias + or_ * 64 + oct0;   // + f*4096
    float* ob       = out + or_ * 64 + oct0;    // + (b*64+f)*4096
#pragma unroll
    for (int i = 0; i < 8; ++i) {
        const int p  = tid + 256 * i;
        const int b_ = p >> 6;
        const int f_ = p & 63;
        const float4 bv0 = *(const float4*)(bb + f_ * 4096);
        const float4 bv1 = *(const float4*)(bb + f_ * 4096 + 4);
        const float* row = OS + b_ * OSM_ROW + f_ * 9;
        float4 o0, o1;
        o0.x = fmaxf(row[0] + bv0.x, 0.f);
        o0.y = fmaxf(row[1] + bv0.y, 0.f);
        o0.z = fmaxf(row[2] + bv0.z, 0.f);
        o0.w = fmaxf(row[3] + bv0.w, 0.f);
        o1.x = fmaxf(row[4] + bv1.x, 0.f);
        o1.y = fmaxf(row[5] + bv1.y, 0.f);
        o1.z = fmaxf(row[6] + bv1.z, 0.f);
        o1.w = fmaxf(row[7] + bv1.w, 0.f);
        float4* dst = (float4*)(ob + (size_t)(b_ * 64 + f_) * 4096);
        dst[0] = o0;
        dst[1] = o1;
    }
}

extern "C" void kernel_launch(void* const* d_in, const int* in_sizes, int n_in,
                              void* d_out, int out_size) {
    const float* x    = (const float*)d_in[0];
    const float* w    = (const float*)d_in[1];
    const float* bias = (const float*)d_in[2];
    float* out        = (float*)d_out;

    cudaFuncSetAttribute(lc2d_kernel,
                         cudaFuncAttributeMaxDynamicSharedMemorySize, SMEM_BYTES);

    dim3 grid(8, 64, 1);
    lc2d_kernel<<<grid, 256, SMEM_BYTES>>>(x, w, bias, out);
}

// round 7
// speedup vs baseline: 2.0239x; 1.0852x over previous
#include <cuda_runtime.h>
#include <cstdint>

#define KA 12                 // k-stride (8 + 4 pad) -> conflict-free fragment LDS
#define AWS 388               // 32*KA + 4  (warp panel stride, A)
#define BWS 772               // 64*KA + 4  (warp panel stride, B)
#define ABUF (8*AWS)          // 3104 floats per A buffer
#define BBUF (8*BWS)          // 6176 floats per B buffer
#define OSM_ROW 581           // 64*9 + 5 (epilogue transpose row stride)
#define SMEM_FLOATS 18592
#define SMEM_BYTES (SMEM_FLOATS*4)

#define PSTEP (16*32*16384)   // +16 in b/f dimension (floats)
#define CSTEP (2*16384)       // +1 stage = +2 channels (floats)

__device__ __forceinline__ uint32_t f2tf32(float f) {
    uint32_t u; asm("cvt.rna.tf32.f32 %0, %1;" : "=r"(u) : "f"(f)); return u;
}
__device__ __forceinline__ void mma_tf32(float& d0, float& d1, float& d2, float& d3,
                                         uint32_t a0, uint32_t a1, uint32_t a2, uint32_t a3,
                                         uint32_t b0, uint32_t b1) {
    asm("mma.sync.aligned.m16n8k8.row.col.f32.tf32.tf32.f32 "
        "{%0,%1,%2,%3},{%4,%5,%6,%7},{%8,%9},{%0,%1,%2,%3};"
        : "+f"(d0), "+f"(d1), "+f"(d2), "+f"(d3)
        : "r"(a0), "r"(a1), "r"(a2), "r"(a3), "r"(b0), "r"(b1));
}

__global__ __launch_bounds__(256, 2)
void lc2d_kernel(const float* __restrict__ x,
                 const float* __restrict__ w,
                 const float* __restrict__ bias,
                 float* __restrict__ out) {
    extern __shared__ float sm[];
    float* AS = sm;                 // [2][warp8][b32][KA]
    float* BS = sm + 2 * ABUF;      // [2][warp8][f64][KA]

    const int tid  = threadIdx.x;
    const int or_  = blockIdx.y;
    const int oct0 = blockIdx.x * 8;
    const int h0   = or_ * 2;
    const int w0   = oct0 * 2;

    // ---- loader mapping: tid -> (colq, row, c_local, b-or-f) ----
    const int colq = tid & 3;            // float4 index along 16 input cols
    const int lrow = (tid >> 2) & 1;     // input row within pooled row
    const int lcl  = (tid >> 3) & 1;     // channel within stage
    const int lb   = tid >> 4;           // 0..15 : b (for x) / f (for W)

    const float* xp = x + ((lb * 32 + lcl) * 128 + h0 + lrow) * 128 + w0 + 4 * colq;
    const float* wp = w + ((lb * 32 + lcl) * 128 + h0 + lrow) * 128 + w0 + 4 * colq;

    // STS offsets: col = 4*colq + e ; wp_e = col>>1 ; cp = col&1 ; k = lcl*4+lrow*2+cp
    int a_off[2][4], b_off[4][4];
#pragma unroll
    for (int e = 0; e < 4; ++e) {
        const int wpe = 2 * colq + (e >> 1);
        const int k   = lcl * 4 + lrow * 2 + (e & 1);
#pragma unroll
        for (int i = 0; i < 2; ++i)
            a_off[i][e] = wpe * AWS + (lb + 16 * i) * KA + k;
#pragma unroll
        for (int i = 0; i < 4; ++i)
            b_off[i][e] = wpe * BWS + (lb + 16 * i) * KA + k;
    }

    // ---- mma mapping ----
    const int lane = tid & 31, wid = tid >> 5;
    const int g = lane >> 2, t = lane & 3;

    int a_ld[2][4];
#pragma unroll
    for (int mt = 0; mt < 2; ++mt) {
        a_ld[mt][0] = wid * AWS + (mt * 16 + g)     * KA + t;
        a_ld[mt][1] = wid * AWS + (mt * 16 + g + 8) * KA + t;
        a_ld[mt][2] = a_ld[mt][0] + 4;
        a_ld[mt][3] = a_ld[mt][1] + 4;
    }

    float acc[2][8][4];
#pragma unroll
    for (int mt = 0; mt < 2; ++mt)
#pragma unroll
        for (int nt = 0; nt < 8; ++nt)
#pragma unroll
            for (int r = 0; r < 4; ++r) acc[mt][nt][r] = 0.f;

    float4 xr[2], wr[4];

    // ---- staging helpers ----
    auto do_ldg = [&](int stage) {
        const int off = stage * CSTEP;
#pragma unroll
        for (int i = 0; i < 2; ++i) xr[i] = *(const float4*)(xp + off + i * PSTEP);
#pragma unroll
        for (int i = 0; i < 4; ++i) wr[i] = *(const float4*)(wp + off + i * PSTEP);
    };
    auto do_sts = [&](int buf) {
        float* An = AS + buf * ABUF;
        float* Bn = BS + buf * BBUF;
#pragma unroll
        for (int i = 0; i < 2; ++i) {
            const float v[4] = {xr[i].x, xr[i].y, xr[i].z, xr[i].w};
#pragma unroll
            for (int e = 0; e < 4; ++e)
                An[a_off[i][e]] = __uint_as_float(f2tf32(v[e]));
        }
#pragma unroll
        for (int i = 0; i < 4; ++i) {
            const float v[4] = {wr[i].x, wr[i].y, wr[i].z, wr[i].w};
#pragma unroll
            for (int e = 0; e < 4; ++e)
                Bn[b_off[i][e]] = __uint_as_float(f2tf32(v[e]));
        }
    };

    // ---- prologue: stage0 -> buf0 ; preload stage1 into regs ----
    do_ldg(0);
    do_sts(0);
    do_ldg(1);
    __syncthreads();

    // ---- main loop: prefetch distance = 1 full stage ----
    for (int s = 0; s < 16; ++s) {
        const int buf = s & 1;

        // 1) stage s+1 data (loaded during stage s-1, long landed) -> idle buffer
        if (s + 1 < 16) do_sts(buf ^ 1);
        // 2) issue loads for stage s+2 into the freed registers
        if (s + 2 < 16) do_ldg(s + 2);

        // 3) compute on buffer `buf`
        const float* Ap = AS + buf * ABUF;
        const float* Bp = BS + buf * BBUF + wid * BWS;

        uint32_t a[2][4];
#pragma unroll
        for (int mt = 0; mt < 2; ++mt)
#pragma unroll
            for (int r = 0; r < 4; ++r)
                a[mt][r] = __float_as_uint(Ap[a_ld[mt][r]]);

#pragma unroll
        for (int nt = 0; nt < 8; ++nt) {
            const uint32_t b0 = __float_as_uint(Bp[(nt * 8 + g) * KA + t]);
            const uint32_t b1 = __float_as_uint(Bp[(nt * 8 + g) * KA + t + 4]);
            mma_tf32(acc[0][nt][0], acc[0][nt][1], acc[0][nt][2], acc[0][nt][3],
                     a[0][0], a[0][1], a[0][2], a[0][3], b0, b1);
            mma_tf32(acc[1][nt][0], acc[1][nt][1], acc[1][nt][2], acc[1][nt][3],
                     a[1][0], a[1][1], a[1][2], a[1][3], b0, b1);
        }

        __syncthreads();
    }

    // ---- epilogue: transpose through smem, bias + relu, coalesced STG ----
    float* OS = sm;   // safe: last stage ended with __syncthreads()
#pragma unroll
    for (int mt = 0; mt < 2; ++mt)
#pragma unroll
        for (int nt = 0; nt < 8; ++nt) {
            const int r0 = mt * 16 + g;
            const int c0 = nt * 8 + 2 * t;
            OS[r0 * OSM_ROW + c0 * 9 + wid]             = acc[mt][nt][0];
            OS[r0 * OSM_ROW + (c0 + 1) * 9 + wid]       = acc[mt][nt][1];
            OS[(r0 + 8) * OSM_ROW + c0 * 9 + wid]       = acc[mt][nt][2];
            OS[(r0 + 8) * OSM_ROW + (c0 + 1) * 9 + wid] = acc[mt][nt][3];
        }
    __syncthreads();

    const float* bb = bias + or_ * 64 + oct0;   // + f*4096
    float* ob       = out + or_ * 64 + oct0;    // + (b*64+f)*4096
#pragma unroll
    for (int i = 0; i < 8; ++i) {
        const int p  = tid + 256 * i;
        const int b_ = p >> 6;
        const int f_ = p & 63;
        const float4 bv0 = *(const float4*)(bb + f_ * 4096);
        const float4 bv1 = *(const float4*)(bb + f_ * 4096 + 4);
        const float* row = OS + b_ * OSM_ROW + f_ * 9;
        float4 o0, o1;
        o0.x = fmaxf(row[0] + bv0.x, 0.f);
        o0.y = fmaxf(row[1] + bv0.y, 0.f);
        o0.z = fmaxf(row[2] + bv0.z, 0.f);
        o0.w = fmaxf(row[3] + bv0.w, 0.f);
        o1.x = fmaxf(row[4] + bv1.x, 0.f);
        o1.y = fmaxf(row[5] + bv1.y, 0.f);
        o1.z = fmaxf(row[6] + bv1.z, 0.f);
        o1.w = fmaxf(row[7] + bv1.w, 0.f);
        float4* dst = (float4*)(ob + (size_t)(b_ * 64 + f_) * 4096);
        dst[0] = o0;
        dst[1] = o1;
    }
}

extern "C" void kernel_launch(void* const* d_in, const int* in_sizes, int n_in,
                              void* d_out, int out_size) {
    const float* x    = (const float*)d_in[0];
    const float* w    = (const float*)d_in[1];
    const float* bias = (const float*)d_in[2];
    float* out        = (float*)d_out;

    cudaFuncSetAttribute(lc2d_kernel,
                         cudaFuncAttributeMaxDynamicSharedMemorySize, SMEM_BYTES);

    dim3 grid(8, 64, 1);
    lc2d_kernel<<<grid, 256, SMEM_BYTES>>>(x, w, bias, out);
}